// round 3
// baseline (speedup 1.0000x reference)
#include <cuda_runtime.h>

// ---------------------------------------------------------------------------
// EMD loss (multiplicative Sinkhorn, 2*eps == 1), FFMA2 (f32x2) GEMM core.
//   per (pair p, batch i): C = row-minmax-norm(1 - cosine(x1[i], x2[i]))
//   E = exp(-2C);  5x { eu = q1 / (ev @ E^T) ; ev = q2 / (eu @ E) }
//   loss += sum eu_j ev_k E_jk C_jk ;  out = total / 8192
// 128 blocks x 256 threads. All GEMM B-operands stored k-PAIRED so the
// reduction runs on packed f32x2 pairs: acc2 += {a_k,a_k+1}*{b_k[e],b_k+1[e]}.
// ---------------------------------------------------------------------------

typedef unsigned long long u64;

#define SMEM_FLOATS 41744
#define SMEM_BYTES (SMEM_FLOATS * 4)

#define OFF_X1   0        // 4096: x1[i] [j][h]
#define OFF_X2P  4096     // 4224: x2[i] h-paired [h2][2e+c], stride 132
#define OFF_C    8320     // 4096: raw 1-cos [j][k]
#define OFF_Q1   12416    // 4096: softmax(x1)+1e-12 [a][j]; later T2
#define OFF_Q2   16512    // 4096
#define OFF_EU   20608    // 4096
#define OFF_EV   24704    // 4096
#define OFF_EP   28800    // 4224: E j-paired  [j2][2k+c]  (v-phase B)
#define OFF_ETP  33024    // 4224: E^T k-paired [k2][2j+c] (u-phase B; later GT)
#define OFF_CTP  37248    // 4224: C^T k-paired
#define OFF_I1   41472    // 64
#define OFF_I2   41536    // 64
#define OFF_RMIN 41600    // 64
#define OFF_RINV 41664    // 64
#define OFF_RED  41728    // 8
#define OFF_FLAG 41736

__device__ float g_partials[128];
__device__ unsigned int g_count = 0;

__device__ __forceinline__ void ff2(u64 &acc, u64 a, u64 b) {
    asm("fma.rn.f32x2 %0, %1, %2, %0;" : "+l"(acc) : "l"(a), "l"(b));
}
__device__ __forceinline__ u64 pack2(float x, float y) {
    u64 p; asm("mov.b64 %0, {%1, %2};" : "=l"(p) : "f"(x), "f"(y)); return p;
}
__device__ __forceinline__ float hsum(u64 p) {
    float x, y;
    asm("mov.b64 {%0, %1}, %2;" : "=f"(x), "=f"(y) : "l"(p));
    return x + y;
}

// acc[f][e] (even/odd-k partial pairs) += sum_k A[(a0+f)*64+k] * B[k][e],
// Bp in k-paired layout: Bp[(k>>1)*132 + 2e + (k&1)].  bc = 2*c0.
__device__ __forceinline__ void pgemm(const float* __restrict__ A,
                                      const float* __restrict__ Bp,
                                      u64 acc[4][4], int a0, int bc)
{
#pragma unroll 4
    for (int kk = 0; kk < 64; kk += 4) {
        const int k2 = kk >> 1;
        ulonglong2 b0 = *(const ulonglong2*)(Bp + k2 * 132 + bc);
        ulonglong2 b1 = *(const ulonglong2*)(Bp + k2 * 132 + bc + 4);
        ulonglong2 d0 = *(const ulonglong2*)(Bp + (k2 + 1) * 132 + bc);
        ulonglong2 d1 = *(const ulonglong2*)(Bp + (k2 + 1) * 132 + bc + 4);
#pragma unroll
        for (int f = 0; f < 4; f++) {
            ulonglong2 av = *(const ulonglong2*)(A + (a0 + f) * 64 + kk);
            ff2(acc[f][0], av.x, b0.x);
            ff2(acc[f][1], av.x, b0.y);
            ff2(acc[f][2], av.x, b1.x);
            ff2(acc[f][3], av.x, b1.y);
            ff2(acc[f][0], av.y, d0.x);
            ff2(acc[f][1], av.y, d0.y);
            ff2(acc[f][2], av.y, d1.x);
            ff2(acc[f][3], av.y, d1.y);
        }
    }
}

__global__ __launch_bounds__(256, 1)
void emd_main(const float* __restrict__ f10, const float* __restrict__ f11,
              const float* __restrict__ f20, const float* __restrict__ f21,
              float* __restrict__ out)
{
    extern __shared__ float sm[];
    const int blk  = blockIdx.x;
    const int pair = blk >> 6;
    const int i    = blk & 63;
    const float* __restrict__ X1g = pair ? f11 : f10;
    const float* __restrict__ X2g = pair ? f21 : f20;

    const int tid  = threadIdx.x;
    const int lane = tid & 31;
    const int wid  = tid >> 5;        // 0..7
    const int ty   = tid >> 4;        // 0..15
    const int tx   = tid & 15;        // 0..15
    const int a0   = ty * 4;
    const int c0   = tx * 4;
    const int bc   = c0 * 2;

    float* sX1  = sm + OFF_X1;
    float* sX2P = sm + OFF_X2P;
    float* sC   = sm + OFF_C;
    float* sQ1  = sm + OFF_Q1;
    float* sQ2  = sm + OFF_Q2;
    float* sEU  = sm + OFF_EU;
    float* sEV  = sm + OFF_EV;
    float* sEP  = sm + OFF_EP;
    float* sETP = sm + OFF_ETP;
    float* sCTP = sm + OFF_CTP;
    float* sI1  = sm + OFF_I1;
    float* sI2  = sm + OFF_I2;
    float* sRmin = sm + OFF_RMIN;
    float* sRinv = sm + OFF_RINV;
    float* sRed  = sm + OFF_RED;
    int*   sFlag = (int*)(sm + OFF_FLAG);

    // ---- load tiles: x1 normal [j][h]; x2 h-paired; fold in raw sumsq ----
    {
        const float4* g1 = (const float4*)(X1g + i * 4096);
        const float4* g2 = (const float4*)(X2g + i * 4096);
#pragma unroll
        for (int m = 0; m < 4; m++) {
            int v = tid + m * 256;               // float4 index 0..1023
            int r  = v >> 4;                     // channel row 0..63
            int hc = v & 15;                     // h-chunk
            float4 a = g1[v];
            ((float4*)sX1)[v] = a;
            float4 b = g2[v];
            *(u64*)(sX2P + (2 * hc) * 132 + 2 * r)     = pack2(b.x, b.y);
            *(u64*)(sX2P + (2 * hc + 1) * 132 + 2 * r) = pack2(b.z, b.w);
            // raw sumsq, reduced over the 16 lanes sharing this row
            float s1 = a.x * a.x + a.y * a.y + a.z * a.z + a.w * a.w;
            float s2 = b.x * b.x + b.y * b.y + b.z * b.z + b.w * b.w;
#pragma unroll
            for (int o = 8; o; o >>= 1) {
                s1 += __shfl_xor_sync(~0u, s1, o);
                s2 += __shfl_xor_sync(~0u, s2, o);
            }
            if ((tid & 15) == 0) { sI1[r] = s1; sI2[r] = s2; }
        }
    }

    // ---- softmax rows: q = softmax(x[a,i,:]) + 1e-12 ----
#pragma unroll 2
    for (int r8 = 0; r8 < 8; r8++) {
        int a = wid * 8 + r8;
        const float* r1 = X1g + (a * 64 + i) * 64;
        const float* r2 = X2g + (a * 64 + i) * 64;
        float x1a = r1[lane], x1b = r1[lane + 32];
        float x2a = r2[lane], x2b = r2[lane + 32];
        {
            float mx = fmaxf(x1a, x1b);
#pragma unroll
            for (int o = 16; o; o >>= 1) mx = fmaxf(mx, __shfl_xor_sync(~0u, mx, o));
            float ex = __expf(x1a - mx), ey = __expf(x1b - mx);
            float s = ex + ey;
#pragma unroll
            for (int o = 16; o; o >>= 1) s += __shfl_xor_sync(~0u, s, o);
            float inv = __fdividef(1.0f, s);
            sQ1[a * 64 + lane]      = ex * inv + 1e-12f;
            sQ1[a * 64 + lane + 32] = ey * inv + 1e-12f;
        }
        {
            float mx = fmaxf(x2a, x2b);
#pragma unroll
            for (int o = 16; o; o >>= 1) mx = fmaxf(mx, __shfl_xor_sync(~0u, mx, o));
            float ex = __expf(x2a - mx), ey = __expf(x2b - mx);
            float s = ex + ey;
#pragma unroll
            for (int o = 16; o; o >>= 1) s += __shfl_xor_sync(~0u, s, o);
            float inv = __fdividef(1.0f, s);
            sQ2[a * 64 + lane]      = ex * inv + 1e-12f;
            sQ2[a * 64 + lane + 32] = ey * inv + 1e-12f;
        }
    }
    __syncthreads();

    // ---- finalize inverse clamped norms ----
    if (tid < 64) {
        sI1[tid] = 1.0f / fmaxf(sqrtf(sI1[tid]), 1e-8f);
        sI2[tid] = 1.0f / fmaxf(sqrtf(sI2[tid]), 1e-8f);
    }
    __syncthreads();

    // ---- C = 1 - cosine: pgemm over h (x1 rows x x2 h-paired) ----
    {
        u64 acc[4][4] = {};
        pgemm(sX1, sX2P, acc, a0, bc);
        float i2v[4];
#pragma unroll
        for (int e = 0; e < 4; e++) i2v[e] = sI2[c0 + e];
#pragma unroll
        for (int f = 0; f < 4; f++) {
            float i1v = sI1[a0 + f];
            float4 r;
            r.x = 1.0f - hsum(acc[f][0]) * i1v * i2v[0];
            r.y = 1.0f - hsum(acc[f][1]) * i1v * i2v[1];
            r.z = 1.0f - hsum(acc[f][2]) * i1v * i2v[2];
            r.w = 1.0f - hsum(acc[f][3]) * i1v * i2v[3];
            *(float4*)(sC + (a0 + f) * 64 + c0) = r;
        }
    }
    __syncthreads();

    // ---- per-row min/max of C ----
#pragma unroll 1
    for (int r8 = 0; r8 < 8; r8++) {
        int row = wid * 8 + r8;
        float x = sC[row * 64 + lane];
        float y = sC[row * 64 + 32 + lane];
        float mn = fminf(x, y), mx = fmaxf(x, y);
#pragma unroll
        for (int o = 16; o; o >>= 1) {
            mn = fminf(mn, __shfl_xor_sync(~0u, mn, o));
            mx = fmaxf(mx, __shfl_xor_sync(~0u, mx, o));
        }
        if (lane == 0) {
            sRmin[row] = mn;
            sRinv[row] = 1.0f / (mx - mn);
        }
    }
    __syncthreads();

    // ---- build paired E^T/C^T (k-paired) and E (j-paired); EV = 1 ----
#pragma unroll
    for (int m = 0; m < 16; m++) {
        int idx = tid + m * 256;
        int j = idx >> 6, k = idx & 63;
        float cn = (sC[idx] - sRmin[j]) * sRinv[j];
        float e  = __expf(-2.0f * cn);
        int posT = (k >> 1) * 132 + 2 * j + (k & 1);
        sETP[posT] = e;
        sCTP[posT] = cn;
        sEP[(j >> 1) * 132 + 2 * k + (j & 1)] = e;
        sEV[idx] = 1.0f;
    }
    __syncthreads();

    // ---- Sinkhorn: 5 Gauss-Seidel iterations ----
#pragma unroll 1
    for (int it = 0; it < 5; it++) {
        {   // u: S[a][j] = sum_k EV[a][k] * ET[k][j];  EU = Q1 / S
            u64 acc[4][4] = {};
            pgemm(sEV, sETP, acc, a0, bc);
#pragma unroll
            for (int f = 0; f < 4; f++) {
                float4 q = *(const float4*)(sQ1 + (a0 + f) * 64 + c0);
                float4 r;
                r.x = __fdividef(q.x, hsum(acc[f][0]));
                r.y = __fdividef(q.y, hsum(acc[f][1]));
                r.z = __fdividef(q.z, hsum(acc[f][2]));
                r.w = __fdividef(q.w, hsum(acc[f][3]));
                *(float4*)(sEU + (a0 + f) * 64 + c0) = r;
            }
        }
        __syncthreads();
        {   // v: T[a][k] = sum_j EU[a][j] * E[j][k];  EV = Q2 / T
            u64 acc[4][4] = {};
            pgemm(sEU, sEP, acc, a0, bc);
#pragma unroll
            for (int f = 0; f < 4; f++) {
                float4 q = *(const float4*)(sQ2 + (a0 + f) * 64 + c0);
                float4 r;
                r.x = __fdividef(q.x, hsum(acc[f][0]));
                r.y = __fdividef(q.y, hsum(acc[f][1]));
                r.z = __fdividef(q.z, hsum(acc[f][2]));
                r.w = __fdividef(q.w, hsum(acc[f][3]));
                *(float4*)(sEV + (a0 + f) * 64 + c0) = r;
            }
        }
        __syncthreads();
    }

    // ---- GT = ET (*) CT in place; T2[a][j] = sum_k EV[a][k]*GT[k][j] ----
#pragma unroll
    for (int m = 0; m < 16; m++) {
        int idx = tid + m * 256;
        int pos = (idx >> 7) * 132 + (idx & 127);
        sETP[pos] *= sCTP[pos];
    }
    __syncthreads();
    {
        u64 acc[4][4] = {};
        pgemm(sEV, sETP, acc, a0, bc);
#pragma unroll
        for (int f = 0; f < 4; f++) {
            float4 r;
            r.x = hsum(acc[f][0]); r.y = hsum(acc[f][1]);
            r.z = hsum(acc[f][2]); r.w = hsum(acc[f][3]);
            *(float4*)(sQ1 + (a0 + f) * 64 + c0) = r;   // Q1 now holds T2
        }
    }
    __syncthreads();

    // ---- block partial: sum EU .* T2 ----
    float local = 0.0f;
#pragma unroll
    for (int m = 0; m < 16; m++) {
        int idx = tid + m * 256;
        local = fmaf(sEU[idx], sQ1[idx], local);
    }
#pragma unroll
    for (int o = 16; o; o >>= 1) local += __shfl_xor_sync(~0u, local, o);
    if (lane == 0) sRed[wid] = local;
    __syncthreads();

    // ---- publish partial; last block does deterministic final reduce ----
    if (tid == 0) {
        float t = 0.0f;
#pragma unroll
        for (int w = 0; w < 8; w++) t += sRed[w];
        g_partials[blk] = t;
        __threadfence();
        unsigned int old = atomicAdd(&g_count, 1u);
        sFlag[0] = (old == 127u);
    }
    __syncthreads();
    if (sFlag[0] && wid == 0) {
        __threadfence();
        float v = g_partials[lane] + g_partials[lane + 32]
                + g_partials[lane + 64] + g_partials[lane + 96];
#pragma unroll
        for (int o = 16; o; o >>= 1) v += __shfl_xor_sync(~0u, v, o);
        if (lane == 0) {
            out[0] = v * (1.0f / 8192.0f);
            g_count = 0;   // reset for next graph replay
        }
    }
}

extern "C" void kernel_launch(void* const* d_in, const int* in_sizes, int n_in,
                              void* d_out, int out_size)
{
    (void)in_sizes; (void)n_in; (void)out_size;
    cudaFuncSetAttribute(emd_main, cudaFuncAttributeMaxDynamicSharedMemorySize, SMEM_BYTES);
    emd_main<<<128, 256, SMEM_BYTES>>>((const float*)d_in[0], (const float*)d_in[1],
                                       (const float*)d_in[2], (const float*)d_in[3],
                                       (float*)d_out);
}

// round 4
// speedup vs baseline: 1.3469x; 1.3469x over previous
#include <cuda_runtime.h>

// ---------------------------------------------------------------------------
// EMD loss (multiplicative Sinkhorn, 2*eps == 1).
//   per (pair p, batch i): C = row-minmax-norm(1 - cosine(x1[i], x2[i]))
//   E = exp(-2C);  eu0 = q1 / rowsum(E);  then
//   { ev = q2 / (eu @ E) ; eu = q1 / (ev @ E^T) } x4 ; ev = q2 / (eu @ E)
//   loss += sum eu_j ev_k E_jk C_jk ;  out = total / 8192
// 128 blocks x 512 threads: split-k GEMMs (two 256-thread groups, 4x4 tiles,
// k-halves), partials combined through conflict-free smem scratch.
// ---------------------------------------------------------------------------

#define SMEM_FLOATS 37332
#define SMEM_BYTES (SMEM_FLOATS * 4)

#define OFF_X1   0        // 4096: x1[i] [j][h]; later E [j][k]
#define OFF_X2   4096     // 4160: x2[i] [k][h] stride 65; later ET/GT [k][j] flat
#define OFF_C    8256     // 4096: raw 1-cos [j][k]
#define OFF_CT   12352    // 4160: C^T [k][j] stride 65
#define OFF_Q1   16512    // 4096
#define OFF_Q2   20608    // 4096
#define OFF_EU   24704    // 4096
#define OFF_EV   28800    // 4096
#define OFF_SCR  32896    // 4096: split-k partials, layout [reg][t] = reg*256+t
#define OFF_I1   36992    // 64
#define OFF_I2   37056    // 64
#define OFF_RS   37120    // 64: 1/rowsum(E)
#define OFF_RMIN 37184    // 64
#define OFF_RINV 37248    // 64
#define OFF_RED  37312    // 8
#define OFF_FLAG 37320

__device__ float g_partials[128];
__device__ unsigned int g_count = 0;

// acc[f][e] += sum_{k in [kb,kb+32)} A[(a0+f)*64+k] * B[k*64+(c0+e)]
// A rows broadcast across 16 lanes; B float4 reads, 2 wavefronts/instr.
__device__ __forceinline__ void half_gemm(const float* __restrict__ A,
                                          const float* __restrict__ B,
                                          float acc[4][4], int a0, int c0, int kb)
{
#pragma unroll 4
    for (int k0 = kb; k0 < kb + 32; k0 += 4) {
        float a_[4][4];
#pragma unroll
        for (int f = 0; f < 4; f++) {
            float4 t = *(const float4*)(A + (a0 + f) * 64 + k0);
            a_[f][0] = t.x; a_[f][1] = t.y; a_[f][2] = t.z; a_[f][3] = t.w;
        }
#pragma unroll
        for (int dk = 0; dk < 4; dk++) {
            float4 b = *(const float4*)(B + (k0 + dk) * 64 + c0);
#pragma unroll
            for (int f = 0; f < 4; f++) {
                acc[f][0] = fmaf(a_[f][dk], b.x, acc[f][0]);
                acc[f][1] = fmaf(a_[f][dk], b.y, acc[f][1]);
                acc[f][2] = fmaf(a_[f][dk], b.z, acc[f][2]);
                acc[f][3] = fmaf(a_[f][dk], b.w, acc[f][3]);
            }
        }
    }
}

__global__ __launch_bounds__(512, 1)
void emd_main(const float* __restrict__ f10, const float* __restrict__ f11,
              const float* __restrict__ f20, const float* __restrict__ f21,
              float* __restrict__ out)
{
    extern __shared__ float sm[];
    const int blk  = blockIdx.x;
    const int pair = blk >> 6;
    const int i    = blk & 63;
    const float* __restrict__ X1g = pair ? f11 : f10;
    const float* __restrict__ X2g = pair ? f21 : f20;

    const int tid  = threadIdx.x;
    const int lane = tid & 31;
    const int wid  = tid >> 5;        // 0..15
    const int grp  = tid >> 8;        // k-half: 0 or 1
    const int t    = tid & 255;
    const int ty   = t >> 4;
    const int tx   = t & 15;
    const int a0   = ty * 4;
    const int c0   = tx * 4;
    const int kb   = grp * 32;

    float* sX1 = sm + OFF_X1;
    float* sX2 = sm + OFF_X2;   // stride 65 while holding x2
    float* sC  = sm + OFF_C;
    float* sCT = sm + OFF_CT;   // stride 65
    float* sQ1 = sm + OFF_Q1;
    float* sQ2 = sm + OFF_Q2;
    float* sEU = sm + OFF_EU;
    float* sEV = sm + OFF_EV;
    float* sScr = sm + OFF_SCR;
    float* sI1 = sm + OFF_I1;
    float* sI2 = sm + OFF_I2;
    float* sRS = sm + OFF_RS;
    float* sRmin = sm + OFF_RMIN;
    float* sRinv = sm + OFF_RINV;
    float* sRed  = sm + OFF_RED;
    int*   sFlag = (int*)(sm + OFF_FLAG);

    // ---- load x1 (flat), x2 (stride 65); fold in raw row sumsq ----
    {
        const float4* g1 = (const float4*)(X1g + i * 4096);
        const float4* g2 = (const float4*)(X2g + i * 4096);
#pragma unroll
        for (int m = 0; m < 2; m++) {
            int v = tid + m * 512;               // float4 index 0..1023
            int r = v >> 4;
            int c = (v & 15) << 2;
            float4 a = g1[v];
            ((float4*)sX1)[v] = a;
            float4 b = g2[v];
            float* dst = sX2 + r * 65 + c;
            dst[0] = b.x; dst[1] = b.y; dst[2] = b.z; dst[3] = b.w;
            float s1 = a.x * a.x + a.y * a.y + a.z * a.z + a.w * a.w;
            float s2 = b.x * b.x + b.y * b.y + b.z * b.z + b.w * b.w;
#pragma unroll
            for (int o = 8; o; o >>= 1) {
                s1 += __shfl_xor_sync(~0u, s1, o);
                s2 += __shfl_xor_sync(~0u, s2, o);
            }
            if ((tid & 15) == 0) { sI1[r] = s1; sI2[r] = s2; }
        }
    }

    // ---- softmax rows: q = softmax(x[a,i,:]) + 1e-12 (8 row-jobs/warp) ----
#pragma unroll 1
    for (int r4 = 0; r4 < 4; r4++) {
        int a = wid * 4 + r4;
        const float* r1 = X1g + (a * 64 + i) * 64;
        const float* r2 = X2g + (a * 64 + i) * 64;
        float x1a = r1[lane], x1b = r1[lane + 32];
        float x2a = r2[lane], x2b = r2[lane + 32];
        {
            float mx = fmaxf(x1a, x1b);
#pragma unroll
            for (int o = 16; o; o >>= 1) mx = fmaxf(mx, __shfl_xor_sync(~0u, mx, o));
            float ex = __expf(x1a - mx), ey = __expf(x1b - mx);
            float s = ex + ey;
#pragma unroll
            for (int o = 16; o; o >>= 1) s += __shfl_xor_sync(~0u, s, o);
            float inv = __fdividef(1.0f, s);
            sQ1[a * 64 + lane]      = ex * inv + 1e-12f;
            sQ1[a * 64 + lane + 32] = ey * inv + 1e-12f;
        }
        {
            float mx = fmaxf(x2a, x2b);
#pragma unroll
            for (int o = 16; o; o >>= 1) mx = fmaxf(mx, __shfl_xor_sync(~0u, mx, o));
            float ex = __expf(x2a - mx), ey = __expf(x2b - mx);
            float s = ex + ey;
#pragma unroll
            for (int o = 16; o; o >>= 1) s += __shfl_xor_sync(~0u, s, o);
            float inv = __fdividef(1.0f, s);
            sQ2[a * 64 + lane]      = ex * inv + 1e-12f;
            sQ2[a * 64 + lane + 32] = ey * inv + 1e-12f;
        }
    }
    __syncthreads();

    // ---- finalize inverse clamped norms ----
    if (tid < 64) {
        sI1[tid] = 1.0f / fmaxf(sqrtf(sI1[tid]), 1e-8f);
        sI2[tid] = 1.0f / fmaxf(sqrtf(sI2[tid]), 1e-8f);
    }
    __syncthreads();

    // ---- C = 1 - cosine (split-h GEMM: x1 rows x x2 rows) ----
    {
        float acc[4][4] = {};
#pragma unroll 4
        for (int h0 = kb; h0 < kb + 32; h0 += 4) {
            float a_[4][4];
#pragma unroll
            for (int f = 0; f < 4; f++) {
                float4 v = *(const float4*)(sX1 + (a0 + f) * 64 + h0);
                a_[f][0] = v.x; a_[f][1] = v.y; a_[f][2] = v.z; a_[f][3] = v.w;
            }
#pragma unroll
            for (int dh = 0; dh < 4; dh++) {
                float b[4];
#pragma unroll
                for (int e = 0; e < 4; e++) b[e] = sX2[(c0 + e) * 65 + h0 + dh];
#pragma unroll
                for (int f = 0; f < 4; f++) {
                    acc[f][0] = fmaf(a_[f][dh], b[0], acc[f][0]);
                    acc[f][1] = fmaf(a_[f][dh], b[1], acc[f][1]);
                    acc[f][2] = fmaf(a_[f][dh], b[2], acc[f][2]);
                    acc[f][3] = fmaf(a_[f][dh], b[3], acc[f][3]);
                }
            }
        }
        if (grp) {
#pragma unroll
            for (int r = 0; r < 16; r++) sScr[r * 256 + t] = acc[r >> 2][r & 3];
        }
        __syncthreads();
        if (!grp) {
            float i2v[4];
#pragma unroll
            for (int e = 0; e < 4; e++) i2v[e] = sI2[c0 + e];
#pragma unroll
            for (int f = 0; f < 4; f++) {
                float i1v = sI1[a0 + f];
                float4 r;
                r.x = 1.0f - (acc[f][0] + sScr[(f * 4 + 0) * 256 + t]) * i1v * i2v[0];
                r.y = 1.0f - (acc[f][1] + sScr[(f * 4 + 1) * 256 + t]) * i1v * i2v[1];
                r.z = 1.0f - (acc[f][2] + sScr[(f * 4 + 2) * 256 + t]) * i1v * i2v[2];
                r.w = 1.0f - (acc[f][3] + sScr[(f * 4 + 3) * 256 + t]) * i1v * i2v[3];
                *(float4*)(sC + (a0 + f) * 64 + c0) = r;
            }
        }
        __syncthreads();
    }

    // ---- per-row min/max of C ----
#pragma unroll 1
    for (int r4 = 0; r4 < 4; r4++) {
        int row = wid * 4 + r4;
        float x = sC[row * 64 + lane];
        float y = sC[row * 64 + 32 + lane];
        float mn = fminf(x, y), mx = fmaxf(x, y);
#pragma unroll
        for (int o = 16; o; o >>= 1) {
            mn = fminf(mn, __shfl_xor_sync(~0u, mn, o));
            mx = fmaxf(mx, __shfl_xor_sync(~0u, mx, o));
        }
        if (lane == 0) {
            sRmin[row] = mn;
            sRinv[row] = 1.0f / (mx - mn);
        }
    }
    __syncthreads();

    // ---- pass1: normalize C -> CT (stride 65), E = exp(-2C) into X1 ----
    float* sE = sX1;
#pragma unroll
    for (int m = 0; m < 8; m++) {
        int idx = tid + m * 512;
        int j = idx >> 6, k = idx & 63;
        float cn = (sC[idx] - sRmin[j]) * sRinv[j];
        sCT[k * 65 + j] = cn;
        sE[idx] = __expf(-2.0f * cn);
    }
    __syncthreads();

    // ---- pass1b: 1/rowsum(E) (first u-update shortcut) ----
#pragma unroll 1
    for (int r4 = 0; r4 < 4; r4++) {
        int row = wid * 4 + r4;
        float s = sE[row * 64 + lane] + sE[row * 64 + 32 + lane];
#pragma unroll
        for (int o = 16; o; o >>= 1) s += __shfl_xor_sync(~0u, s, o);
        if (lane == 0) sRS[row] = __fdividef(1.0f, s);
    }
    __syncthreads();

    // ---- pass2: ET[k][j] from CT (coalesced); EU = Q1 * (1/rowsum) ----
    float* sET = sX2;   // flat stride-64 now
#pragma unroll
    for (int m = 0; m < 8; m++) {
        int idx = tid + m * 512;
        int k = idx >> 6, j = idx & 63;
        sET[idx] = __expf(-2.0f * sCT[k * 65 + j]);
        sEU[idx] = sQ1[idx] * sRS[j];   // idx as [a][j]
    }
    __syncthreads();

    // ---- Sinkhorn: 5 v-phases, 4 u-phases (first u folded above) ----
#pragma unroll 1
    for (int it = 0; it < 5; it++) {
        {   // v: T[a][k] = sum_j EU[a][j] * E[j][k];  EV = Q2 / T
            float acc[4][4] = {};
            half_gemm(sEU, sE, acc, a0, c0, kb);
            if (grp) {
#pragma unroll
                for (int r = 0; r < 16; r++) sScr[r * 256 + t] = acc[r >> 2][r & 3];
            }
            __syncthreads();
            if (!grp) {
#pragma unroll
                for (int f = 0; f < 4; f++) {
                    float4 q = *(const float4*)(sQ2 + (a0 + f) * 64 + c0);
                    float4 r;
                    r.x = __fdividef(q.x, acc[f][0] + sScr[(f * 4 + 0) * 256 + t]);
                    r.y = __fdividef(q.y, acc[f][1] + sScr[(f * 4 + 1) * 256 + t]);
                    r.z = __fdividef(q.z, acc[f][2] + sScr[(f * 4 + 2) * 256 + t]);
                    r.w = __fdividef(q.w, acc[f][3] + sScr[(f * 4 + 3) * 256 + t]);
                    *(float4*)(sEV + (a0 + f) * 64 + c0) = r;
                }
            }
            __syncthreads();
        }
        if (it == 4) break;
        {   // u: S[a][j] = sum_k EV[a][k] * ET[k][j];  EU = Q1 / S
            float acc[4][4] = {};
            half_gemm(sEV, sET, acc, a0, c0, kb);
            if (grp) {
#pragma unroll
                for (int r = 0; r < 16; r++) sScr[r * 256 + t] = acc[r >> 2][r & 3];
            }
            __syncthreads();
            if (!grp) {
#pragma unroll
                for (int f = 0; f < 4; f++) {
                    float4 q = *(const float4*)(sQ1 + (a0 + f) * 64 + c0);
                    float4 r;
                    r.x = __fdividef(q.x, acc[f][0] + sScr[(f * 4 + 0) * 256 + t]);
                    r.y = __fdividef(q.y, acc[f][1] + sScr[(f * 4 + 1) * 256 + t]);
                    r.z = __fdividef(q.z, acc[f][2] + sScr[(f * 4 + 2) * 256 + t]);
                    r.w = __fdividef(q.w, acc[f][3] + sScr[(f * 4 + 3) * 256 + t]);
                    *(float4*)(sEU + (a0 + f) * 64 + c0) = r;
                }
            }
            __syncthreads();
        }
    }

    // ---- GT[k][j] = ET * CT (in place); final GEMM fused with loss dot ----
#pragma unroll
    for (int m = 0; m < 8; m++) {
        int idx = tid + m * 512;
        int k = idx >> 6, j = idx & 63;
        sET[idx] *= sCT[k * 65 + j];
    }
    __syncthreads();
    float local = 0.0f;
    {
        float acc[4][4] = {};
        half_gemm(sEV, sET, acc, a0, c0, kb);
        if (grp) {
#pragma unroll
            for (int r = 0; r < 16; r++) sScr[r * 256 + t] = acc[r >> 2][r & 3];
        }
        __syncthreads();
        if (!grp) {
#pragma unroll
            for (int f = 0; f < 4; f++) {
#pragma unroll
                for (int e = 0; e < 4; e++) {
                    float t2 = acc[f][e] + sScr[(f * 4 + e) * 256 + t];
                    local = fmaf(sEU[(a0 + f) * 64 + c0 + e], t2, local);
                }
            }
        }
    }
#pragma unroll
    for (int o = 16; o; o >>= 1) local += __shfl_xor_sync(~0u, local, o);
    if (!grp && lane == 0) sRed[wid] = local;
    __syncthreads();

    // ---- publish partial; last block does deterministic final reduce ----
    if (tid == 0) {
        float tt = 0.0f;
#pragma unroll
        for (int w = 0; w < 8; w++) tt += sRed[w];
        g_partials[blk] = tt;
        __threadfence();
        unsigned int old = atomicAdd(&g_count, 1u);
        sFlag[0] = (old == 127u);
    }
    __syncthreads();
    if (sFlag[0] && wid == 0) {
        __threadfence();
        float v = g_partials[lane] + g_partials[lane + 32]
                + g_partials[lane + 64] + g_partials[lane + 96];
#pragma unroll
        for (int o = 16; o; o >>= 1) v += __shfl_xor_sync(~0u, v, o);
        if (lane == 0) {
            out[0] = v * (1.0f / 8192.0f);
            g_count = 0;   // reset for next graph replay
        }
    }
}

extern "C" void kernel_launch(void* const* d_in, const int* in_sizes, int n_in,
                              void* d_out, int out_size)
{
    (void)in_sizes; (void)n_in; (void)out_size;
    cudaFuncSetAttribute(emd_main, cudaFuncAttributeMaxDynamicSharedMemorySize, SMEM_BYTES);
    emd_main<<<128, 512, SMEM_BYTES>>>((const float*)d_in[0], (const float*)d_in[1],
                                       (const float*)d_in[2], (const float*)d_in[3],
                                       (float*)d_out);
}

// round 5
// speedup vs baseline: 2.4866x; 1.8462x over previous
#include <cuda_runtime.h>
#include <cuda_bf16.h>

// ---------------------------------------------------------------------------
// EMD loss (multiplicative Sinkhorn, 2*eps == 1), HMMA (bf16 mma.sync) core.
//   C = row-minmax-norm(1 - cos(x1[i],x2[i]))  [fp32 scalar GEMM]
//   E = exp(-2C);  eu0 = q1/rowsum(E);
//   {ev = q2/(eu@E) ; eu = q1/(ev@E^T)} x4 ; ev = q2/(eu@E)   [bf16 HMMA]
//   loss += eu^T (E.*C) ev   [bf16 HMMA]
// 128 blocks x 512 threads. bf16 buffers row-stride 72 (ET: 74) -> all
// fragment LDS/STS conflict-free. Warp w owns output rows 16*(w&3),
// cols 16*(w>>2): 2 m16n8k16 tiles, epilogue division in-warp.
// ---------------------------------------------------------------------------

#define SMEM_BYTES 116608

// byte offsets
#define OB_X1    0        // f32 x1 [j][h] flat          (16384)
#define OB_X2P   16384    // f32 x2 [k][h] stride 65     (16640)
#define OB_C68   33024    // f32 raw C [j][k] stride 68  (17408)
#define OB_Q1B   50432    // bf16 q1 [a][j] stride 72    (9216)
#define OB_Q2B   59648    // bf16 q2 [a][k]              (9216)
#define OB_EB    68864    // bf16 E  [j][k]              (9216)
#define OB_ETB   78080    // bf16 E^T [k][j] stride 74   (9472)
#define OB_GB    87552    // bf16 E.*C [j][k]            (9216)
#define OB_EUB   96768    // bf16 eu [a][j]              (9216)
#define OB_EVB   105984   // bf16 ev [a][k]              (9216)
#define OB_I1    115200
#define OB_I2    115456
#define OB_RS    115712
#define OB_RMIN  115968
#define OB_RINV  116224
#define OB_RED   116480
#define OB_FLAG  116544
#define OB_SCR   68864    // f32 cosine split-k scratch (16KB), aliases EB/ETB

#define STW 36            // bf16 row stride in 32-bit words
#define STTW 37           // ET row stride in words

__device__ float g_partials[128];
__device__ unsigned int g_count = 0;

__device__ __forceinline__ void mma_bf16(float c[4], unsigned a0, unsigned a1,
                                         unsigned a2, unsigned a3,
                                         unsigned b0, unsigned b1)
{
    asm volatile(
        "mma.sync.aligned.m16n8k16.row.col.f32.bf16.bf16.f32 "
        "{%0,%1,%2,%3}, {%4,%5,%6,%7}, {%8,%9}, {%0,%1,%2,%3};"
        : "+f"(c[0]), "+f"(c[1]), "+f"(c[2]), "+f"(c[3])
        : "r"(a0), "r"(a1), "r"(a2), "r"(a3), "r"(b0), "r"(b1));
}

__device__ __forceinline__ float2 unpack_bf2(unsigned w) {
    __nv_bfloat162 h = *reinterpret_cast<__nv_bfloat162*>(&w);
    return __bfloat1622float2(h);
}
__device__ __forceinline__ unsigned pack_bf2(float lo, float hi) {
    __nv_bfloat162 h = __floats2bfloat162_rn(lo, hi);
    return *reinterpret_cast<unsigned*>(&h);
}

// One 64x64x64 GEMM phase on bf16 operands + fp32 epilogue division.
// out[r][c] = sum_k A[r][k] * Bt[c][k];  Dst = Q / out (bf16).
__device__ __forceinline__ void mma_div_phase(
    const unsigned* __restrict__ A32, const unsigned* __restrict__ B32,
    int bstw, const unsigned* __restrict__ Q32, unsigned* __restrict__ D32,
    int wid, int lane)
{
    const int rb = wid & 3, cb = wid >> 2;
    const int g = lane >> 2, tg = lane & 3;
    const int r0 = rb * 16;
    float acc[2][4] = {};
    const int abase = (r0 + g) * STW + tg;
#pragma unroll
    for (int kc = 0; kc < 4; kc++) {
        unsigned a0 = A32[abase + 8 * kc];
        unsigned a1 = A32[abase + 8 * STW + 8 * kc];
        unsigned a2 = A32[abase + 8 * kc + 4];
        unsigned a3 = A32[abase + 8 * STW + 8 * kc + 4];
#pragma unroll
        for (int t = 0; t < 2; t++) {
            int bbase = (cb * 16 + 8 * t + g) * bstw + tg;
            unsigned b0 = B32[bbase + 8 * kc];
            unsigned b1 = B32[bbase + 8 * kc + 4];
            mma_bf16(acc[t], a0, a1, a2, a3, b0, b1);
        }
    }
#pragma unroll
    for (int t = 0; t < 2; t++) {
        int colw = cb * 8 + 4 * t + tg;           // column pair (word) index
        int rlo = r0 + g, rhi = rlo + 8;
        float2 ql = unpack_bf2(Q32[rlo * STW + colw]);
        float2 qh = unpack_bf2(Q32[rhi * STW + colw]);
        D32[rlo * STW + colw] = pack_bf2(__fdividef(ql.x, acc[t][0]),
                                         __fdividef(ql.y, acc[t][1]));
        D32[rhi * STW + colw] = pack_bf2(__fdividef(qh.x, acc[t][2]),
                                         __fdividef(qh.y, acc[t][3]));
    }
}

__global__ __launch_bounds__(512, 1)
void emd_main(const float* __restrict__ f10, const float* __restrict__ f11,
              const float* __restrict__ f20, const float* __restrict__ f21,
              float* __restrict__ out)
{
    extern __shared__ char smb[];
    const int blk  = blockIdx.x;
    const int pair = blk >> 6;
    const int i    = blk & 63;
    const float* __restrict__ X1g = pair ? f11 : f10;
    const float* __restrict__ X2g = pair ? f21 : f20;

    const int tid  = threadIdx.x;
    const int lane = tid & 31;
    const int wid  = tid >> 5;        // 0..15
    const int grp  = tid >> 8;        // cosine k-half
    const int t    = tid & 255;
    const int ty   = t >> 4;
    const int tx   = t & 15;
    const int a0   = ty * 4;
    const int c0   = tx * 4;
    const int kb   = grp * 32;

    float* sX1  = (float*)(smb + OB_X1);
    float* sX2  = (float*)(smb + OB_X2P);
    float* sC   = (float*)(smb + OB_C68);
    float* sScr = (float*)(smb + OB_SCR);
    float* sI1  = (float*)(smb + OB_I1);
    float* sI2  = (float*)(smb + OB_I2);
    float* sRS  = (float*)(smb + OB_RS);
    float* sRmin = (float*)(smb + OB_RMIN);
    float* sRinv = (float*)(smb + OB_RINV);
    float* sRed  = (float*)(smb + OB_RED);
    int*   sFlag = (int*)(smb + OB_FLAG);
    __nv_bfloat16* sQ1b = (__nv_bfloat16*)(smb + OB_Q1B);
    __nv_bfloat16* sQ2b = (__nv_bfloat16*)(smb + OB_Q2B);
    __nv_bfloat16* sEb  = (__nv_bfloat16*)(smb + OB_EB);
    __nv_bfloat16* sETb = (__nv_bfloat16*)(smb + OB_ETB);
    unsigned* Q1_32 = (unsigned*)(smb + OB_Q1B);
    unsigned* Q2_32 = (unsigned*)(smb + OB_Q2B);
    unsigned* E_32  = (unsigned*)(smb + OB_EB);
    unsigned* ET_32 = (unsigned*)(smb + OB_ETB);
    unsigned* G_32  = (unsigned*)(smb + OB_GB);
    unsigned* EU_32 = (unsigned*)(smb + OB_EUB);
    unsigned* EV_32 = (unsigned*)(smb + OB_EVB);

    // ---- load x1 (flat), x2 (stride 65); raw row sumsq folded in ----
    {
        const float4* g1 = (const float4*)(X1g + i * 4096);
        const float4* g2 = (const float4*)(X2g + i * 4096);
#pragma unroll
        for (int m = 0; m < 2; m++) {
            int v = tid + m * 512;
            int r = v >> 4;
            int c = (v & 15) << 2;
            float4 a = g1[v];
            ((float4*)sX1)[v] = a;
            float4 b = g2[v];
            float* dst = sX2 + r * 65 + c;
            dst[0] = b.x; dst[1] = b.y; dst[2] = b.z; dst[3] = b.w;
            float s1 = a.x * a.x + a.y * a.y + a.z * a.z + a.w * a.w;
            float s2 = b.x * b.x + b.y * b.y + b.z * b.z + b.w * b.w;
#pragma unroll
            for (int o = 8; o; o >>= 1) {
                s1 += __shfl_xor_sync(~0u, s1, o);
                s2 += __shfl_xor_sync(~0u, s2, o);
            }
            if ((tid & 15) == 0) { sI1[r] = s1; sI2[r] = s2; }
        }
    }

    // ---- softmax -> q (bf16, stride 72) ----
#pragma unroll 1
    for (int r4 = 0; r4 < 4; r4++) {
        int a = wid * 4 + r4;
        const float* r1 = X1g + (a * 64 + i) * 64;
        const float* r2 = X2g + (a * 64 + i) * 64;
        float x1a = r1[lane], x1b = r1[lane + 32];
        float x2a = r2[lane], x2b = r2[lane + 32];
        {
            float mx = fmaxf(x1a, x1b);
#pragma unroll
            for (int o = 16; o; o >>= 1) mx = fmaxf(mx, __shfl_xor_sync(~0u, mx, o));
            float ex = __expf(x1a - mx), ey = __expf(x1b - mx);
            float s = ex + ey;
#pragma unroll
            for (int o = 16; o; o >>= 1) s += __shfl_xor_sync(~0u, s, o);
            float inv = __fdividef(1.0f, s);
            sQ1b[a * 72 + lane]      = __float2bfloat16(ex * inv + 1e-12f);
            sQ1b[a * 72 + lane + 32] = __float2bfloat16(ey * inv + 1e-12f);
        }
        {
            float mx = fmaxf(x2a, x2b);
#pragma unroll
            for (int o = 16; o; o >>= 1) mx = fmaxf(mx, __shfl_xor_sync(~0u, mx, o));
            float ex = __expf(x2a - mx), ey = __expf(x2b - mx);
            float s = ex + ey;
#pragma unroll
            for (int o = 16; o; o >>= 1) s += __shfl_xor_sync(~0u, s, o);
            float inv = __fdividef(1.0f, s);
            sQ2b[a * 72 + lane]      = __float2bfloat16(ex * inv + 1e-12f);
            sQ2b[a * 72 + lane + 32] = __float2bfloat16(ey * inv + 1e-12f);
        }
    }
    __syncthreads();

    if (tid < 64) {
        sI1[tid] = 1.0f / fmaxf(sqrtf(sI1[tid]), 1e-8f);
        sI2[tid] = 1.0f / fmaxf(sqrtf(sI2[tid]), 1e-8f);
    }
    __syncthreads();

    // ---- C = 1 - cosine (fp32 split-k GEMM) -> C68 ----
    {
        float acc[4][4] = {};
#pragma unroll 4
        for (int h0 = kb; h0 < kb + 32; h0 += 4) {
            float a_[4][4];
#pragma unroll
            for (int f = 0; f < 4; f++) {
                float4 v = *(const float4*)(sX1 + (a0 + f) * 64 + h0);
                a_[f][0] = v.x; a_[f][1] = v.y; a_[f][2] = v.z; a_[f][3] = v.w;
            }
#pragma unroll
            for (int dh = 0; dh < 4; dh++) {
                float b[4];
#pragma unroll
                for (int e = 0; e < 4; e++) b[e] = sX2[(c0 + e) * 65 + h0 + dh];
#pragma unroll
                for (int f = 0; f < 4; f++) {
                    acc[f][0] = fmaf(a_[f][dh], b[0], acc[f][0]);
                    acc[f][1] = fmaf(a_[f][dh], b[1], acc[f][1]);
                    acc[f][2] = fmaf(a_[f][dh], b[2], acc[f][2]);
                    acc[f][3] = fmaf(a_[f][dh], b[3], acc[f][3]);
                }
            }
        }
        if (grp) {
#pragma unroll
            for (int r = 0; r < 16; r++) sScr[r * 256 + t] = acc[r >> 2][r & 3];
        }
        __syncthreads();
        if (!grp) {
            float i2v[4];
#pragma unroll
            for (int e = 0; e < 4; e++) i2v[e] = sI2[c0 + e];
#pragma unroll
            for (int f = 0; f < 4; f++) {
                float i1v = sI1[a0 + f];
                float4 r;
                r.x = 1.0f - (acc[f][0] + sScr[(f * 4 + 0) * 256 + t]) * i1v * i2v[0];
                r.y = 1.0f - (acc[f][1] + sScr[(f * 4 + 1) * 256 + t]) * i1v * i2v[1];
                r.z = 1.0f - (acc[f][2] + sScr[(f * 4 + 2) * 256 + t]) * i1v * i2v[2];
                r.w = 1.0f - (acc[f][3] + sScr[(f * 4 + 3) * 256 + t]) * i1v * i2v[3];
                *(float4*)(sC + (a0 + f) * 68 + c0) = r;
            }
        }
        __syncthreads();
    }

    // ---- per-row min/max of C ----
#pragma unroll 1
    for (int r4 = 0; r4 < 4; r4++) {
        int row = wid * 4 + r4;
        float x = sC[row * 68 + lane];
        float y = sC[row * 68 + 32 + lane];
        float mn = fminf(x, y), mx = fmaxf(x, y);
#pragma unroll
        for (int o = 16; o; o >>= 1) {
            mn = fminf(mn, __shfl_xor_sync(~0u, mn, o));
            mx = fmaxf(mx, __shfl_xor_sync(~0u, mx, o));
        }
        if (lane == 0) {
            sRmin[row] = mn;
            sRinv[row] = 1.0f / (mx - mn);
        }
    }
    __syncthreads();

    // ---- build E (bf16), E^T, G = E.*C (bf16); rowsum(E) shortcut ----
    {
        int j = tid >> 3, k0 = (tid & 7) * 8;
        float4 cA = *(const float4*)(sC + j * 68 + k0);
        float4 cB = *(const float4*)(sC + j * 68 + k0 + 4);
        float cv[8] = {cA.x, cA.y, cA.z, cA.w, cB.x, cB.y, cB.z, cB.w};
        float mn = sRmin[j], ri = sRinv[j];
        float ev[8], s = 0.0f;
#pragma unroll
        for (int d = 0; d < 8; d++) {
            float cn = (cv[d] - mn) * ri;
            cv[d] = cn;
            ev[d] = __expf(-2.0f * cn);
            s += ev[d];
        }
#pragma unroll
        for (int p = 0; p < 4; p++) {
            E_32[j * STW + (k0 >> 1) + p] = pack_bf2(ev[2 * p], ev[2 * p + 1]);
            G_32[j * STW + (k0 >> 1) + p] =
                pack_bf2(ev[2 * p] * cv[2 * p], ev[2 * p + 1] * cv[2 * p + 1]);
        }
#pragma unroll
        for (int d = 0; d < 8; d++)
            sETb[(k0 + d) * 74 + j] = __float2bfloat16(ev[d]);
#pragma unroll
        for (int o = 4; o; o >>= 1) s += __shfl_xor_sync(~0u, s, o);
        if ((tid & 7) == 0) sRS[j] = __fdividef(1.0f, s);
    }
    __syncthreads();

    // ---- EU0 = q1 * (1/rowsumE) ----
    {
        int a = tid >> 3, j0 = (tid & 7) * 8;
#pragma unroll
        for (int p = 0; p < 4; p++) {
            float2 q = unpack_bf2(Q1_32[a * STW + (j0 >> 1) + p]);
            EU_32[a * STW + (j0 >> 1) + p] =
                pack_bf2(q.x * sRS[j0 + 2 * p], q.y * sRS[j0 + 2 * p + 1]);
        }
    }
    __syncthreads();

    // ---- Sinkhorn: 5 v-phases, 4 u-phases (first u folded) ----
#pragma unroll 1
    for (int it = 0; it < 5; it++) {
        // v: T[a][k] = sum_j EU[a][j] * ET[k][j]-as-Bt;  EV = Q2 / T
        mma_div_phase(EU_32, ET_32, STTW, Q2_32, EV_32, wid, lane);
        __syncthreads();
        if (it == 4) break;
        // u: S[a][j] = sum_k EV[a][k] * E[j][k]-as-Bt;  EU = Q1 / S
        mma_div_phase(EV_32, E_32, STW, Q1_32, EU_32, wid, lane);
        __syncthreads();
    }

    // ---- final: T2 = EV @ G^T(as Bt rows [j][k]);  loss = sum EU .* T2 ----
    float local = 0.0f;
    {
        const int rb = wid & 3, cb = wid >> 2;
        const int g = lane >> 2, tg = lane & 3;
        const int r0 = rb * 16;
        float acc[2][4] = {};
        const int abase = (r0 + g) * STW + tg;
#pragma unroll
        for (int kc = 0; kc < 4; kc++) {
            unsigned a0_ = EV_32[abase + 8 * kc];
            unsigned a1_ = EV_32[abase + 8 * STW + 8 * kc];
            unsigned a2_ = EV_32[abase + 8 * kc + 4];
            unsigned a3_ = EV_32[abase + 8 * STW + 8 * kc + 4];
#pragma unroll
            for (int tt = 0; tt < 2; tt++) {
                int bbase = (cb * 16 + 8 * tt + g) * STW + tg;
                mma_bf16(acc[tt], a0_, a1_, a2_, a3_,
                         G_32[bbase + 8 * kc], G_32[bbase + 8 * kc + 4]);
            }
        }
#pragma unroll
        for (int tt = 0; tt < 2; tt++) {
            int colw = cb * 8 + 4 * tt + tg;
            int rlo = r0 + g, rhi = rlo + 8;
            float2 el = unpack_bf2(EU_32[rlo * STW + colw]);
            float2 eh = unpack_bf2(EU_32[rhi * STW + colw]);
            local += el.x * acc[tt][0] + el.y * acc[tt][1]
                   + eh.x * acc[tt][2] + eh.y * acc[tt][3];
        }
    }
#pragma unroll
    for (int o = 16; o; o >>= 1) local += __shfl_xor_sync(~0u, local, o);
    if (lane == 0) sRed[wid] = local;
    __syncthreads();

    // ---- publish partial; last block reduces deterministically ----
    if (tid == 0) {
        float tt = 0.0f;
#pragma unroll
        for (int w = 0; w < 16; w++) tt += sRed[w];
        g_partials[blk] = tt;
        __threadfence();
        unsigned int old = atomicAdd(&g_count, 1u);
        sFlag[0] = (old == 127u);
    }
    __syncthreads();
    if (sFlag[0] && wid == 0) {
        __threadfence();
        float v = g_partials[lane] + g_partials[lane + 32]
                + g_partials[lane + 64] + g_partials[lane + 96];
#pragma unroll
        for (int o = 16; o; o >>= 1) v += __shfl_xor_sync(~0u, v, o);
        if (lane == 0) {
            out[0] = v * (1.0f / 8192.0f);
            g_count = 0;
        }
    }
}

extern "C" void kernel_launch(void* const* d_in, const int* in_sizes, int n_in,
                              void* d_out, int out_size)
{
    (void)in_sizes; (void)n_in; (void)out_size;
    cudaFuncSetAttribute(emd_main, cudaFuncAttributeMaxDynamicSharedMemorySize, SMEM_BYTES);
    emd_main<<<128, 512, SMEM_BYTES>>>((const float*)d_in[0], (const float*)d_in[1],
                                       (const float*)d_in[2], (const float*)d_in[3],
                                       (float*)d_out);
}

// round 7
// speedup vs baseline: 2.8163x; 1.1326x over previous
#include <cuda_runtime.h>
#include <cuda_bf16.h>

// ---------------------------------------------------------------------------
// EMD loss (multiplicative Sinkhorn, 2*eps == 1), full tensor-core core.
//   C = row-minmax-norm(1 - cos(x1[i],x2[i]))   [tf32 mma.m16n8k8]
//   E = exp(-2C);  eu0 = q1/rowsum(E);
//   {ev = q2/(eu@E) ; eu = q1/(ev@E^T)} x4 ; ev = q2/(eu@E)   [bf16 HMMA]
//   loss += eu^T (E.*C) ev                                     [bf16 HMMA]
// 128 blocks x 512 threads. fp32 buffers stride 68 (x1/x2 tf32-prerounded, C),
// bf16 buffers stride 72 (ET: 74) -> all fragment LDS/STS conflict-free.
// ---------------------------------------------------------------------------

#define SMEM_BYTES 117888

#define OB_X1    0        // f32(tf32) x1 [j][h] stride 68  (17408)
#define OB_X2    17408    // f32(tf32) x2 [k][h] stride 68  (17408)
#define OB_C     34816    // f32 C [j][k] stride 68         (17408)
#define OB_Q1B   52224    // bf16 q1 [a][j] stride 72       (9216)
#define OB_Q2B   61440    // bf16 q2 [a][k]                 (9216)
#define OB_EB    70656    // bf16 E  [j][k]                 (9216)
#define OB_ETB   79872    // bf16 E^T [k][j] stride 74      (9472)
#define OB_GB    89344    // bf16 E.*C [j][k]               (9216)
#define OB_EUB   98560    // bf16 eu [a][j]                 (9216)
#define OB_EVB   107776   // bf16 ev [a][k]                 (9216)
#define OB_I1    116992
#define OB_I2    117248
#define OB_RS    117504
#define OB_RED   117760
#define OB_FLAG  117824

#define STF 68            // fp32 row stride (words)
#define STW 36            // bf16 row stride in 32-bit words
#define STTW 37           // ET row stride in words

__device__ float g_partials[128];
__device__ unsigned int g_count = 0;

__device__ __forceinline__ float tf32r(float x) {
    float r; asm("cvt.rna.tf32.f32 %0, %1;" : "=f"(r) : "f"(x)); return r;
}

__device__ __forceinline__ void mma_bf16(float c[4], unsigned a0, unsigned a1,
                                         unsigned a2, unsigned a3,
                                         unsigned b0, unsigned b1)
{
    asm volatile(
        "mma.sync.aligned.m16n8k16.row.col.f32.bf16.bf16.f32 "
        "{%0,%1,%2,%3}, {%4,%5,%6,%7}, {%8,%9}, {%0,%1,%2,%3};"
        : "+f"(c[0]), "+f"(c[1]), "+f"(c[2]), "+f"(c[3])
        : "r"(a0), "r"(a1), "r"(a2), "r"(a3), "r"(b0), "r"(b1));
}

__device__ __forceinline__ void mma_tf32(float c[4], float a0, float a1,
                                         float a2, float a3, float b0, float b1)
{
    asm volatile(
        "mma.sync.aligned.m16n8k8.row.col.f32.tf32.tf32.f32 "
        "{%0,%1,%2,%3}, {%4,%5,%6,%7}, {%8,%9}, {%0,%1,%2,%3};"
        : "+f"(c[0]), "+f"(c[1]), "+f"(c[2]), "+f"(c[3])
        : "f"(a0), "f"(a1), "f"(a2), "f"(a3), "f"(b0), "f"(b1));
}

__device__ __forceinline__ float2 unpack_bf2(unsigned w) {
    __nv_bfloat162 h = *reinterpret_cast<__nv_bfloat162*>(&w);
    return __bfloat1622float2(h);
}
__device__ __forceinline__ unsigned pack_bf2(float lo, float hi) {
    __nv_bfloat162 h = __floats2bfloat162_rn(lo, hi);
    return *reinterpret_cast<unsigned*>(&h);
}

// One 64x64x64 bf16 GEMM phase + fp32 epilogue division.
// out[r][c] = sum_k A[r][k] * Bt[c][k];  Dst = Q / out (bf16).
__device__ __forceinline__ void mma_div_phase(
    const unsigned* __restrict__ A32, const unsigned* __restrict__ B32,
    int bstw, const unsigned* __restrict__ Q32, unsigned* __restrict__ D32,
    int wid, int lane)
{
    const int rb = wid & 3, cb = wid >> 2;
    const int g = lane >> 2, tg = lane & 3;
    const int r0 = rb * 16;
    float acc[2][4] = {};
    const int abase = (r0 + g) * STW + tg;
#pragma unroll
    for (int kc = 0; kc < 4; kc++) {
        unsigned a0 = A32[abase + 8 * kc];
        unsigned a1 = A32[abase + 8 * STW + 8 * kc];
        unsigned a2 = A32[abase + 8 * kc + 4];
        unsigned a3 = A32[abase + 8 * STW + 8 * kc + 4];
#pragma unroll
        for (int t = 0; t < 2; t++) {
            int bbase = (cb * 16 + 8 * t + g) * bstw + tg;
            unsigned b0 = B32[bbase + 8 * kc];
            unsigned b1 = B32[bbase + 8 * kc + 4];
            mma_bf16(acc[t], a0, a1, a2, a3, b0, b1);
        }
    }
#pragma unroll
    for (int t = 0; t < 2; t++) {
        int colw = cb * 8 + 4 * t + tg;
        int rlo = r0 + g, rhi = rlo + 8;
        float2 ql = unpack_bf2(Q32[rlo * STW + colw]);
        float2 qh = unpack_bf2(Q32[rhi * STW + colw]);
        D32[rlo * STW + colw] = pack_bf2(__fdividef(ql.x, acc[t][0]),
                                         __fdividef(ql.y, acc[t][1]));
        D32[rhi * STW + colw] = pack_bf2(__fdividef(qh.x, acc[t][2]),
                                         __fdividef(qh.y, acc[t][3]));
    }
}

__global__ __launch_bounds__(512, 1)
void emd_main(const float* __restrict__ f10, const float* __restrict__ f11,
              const float* __restrict__ f20, const float* __restrict__ f21,
              float* __restrict__ out)
{
    extern __shared__ char smb[];
    const int blk  = blockIdx.x;
    const int pair = blk >> 6;
    const int i    = blk & 63;
    const float* __restrict__ X1g = pair ? f11 : f10;
    const float* __restrict__ X2g = pair ? f21 : f20;

    const int tid  = threadIdx.x;
    const int lane = tid & 31;
    const int wid  = tid >> 5;        // 0..15

    float* sX1 = (float*)(smb + OB_X1);
    float* sX2 = (float*)(smb + OB_X2);
    float* sC  = (float*)(smb + OB_C);
    float* sI1 = (float*)(smb + OB_I1);
    float* sI2 = (float*)(smb + OB_I2);
    float* sRS = (float*)(smb + OB_RS);
    float* sRed = (float*)(smb + OB_RED);
    int*   sFlag = (int*)(smb + OB_FLAG);
    __nv_bfloat16* sQ1b = (__nv_bfloat16*)(smb + OB_Q1B);
    __nv_bfloat16* sQ2b = (__nv_bfloat16*)(smb + OB_Q2B);
    __nv_bfloat16* sEb  = (__nv_bfloat16*)(smb + OB_EB);
    __nv_bfloat16* sETb = (__nv_bfloat16*)(smb + OB_ETB);
    __nv_bfloat16* sGb  = (__nv_bfloat16*)(smb + OB_GB);
    unsigned* Q1_32 = (unsigned*)(smb + OB_Q1B);
    unsigned* Q2_32 = (unsigned*)(smb + OB_Q2B);
    unsigned* E_32  = (unsigned*)(smb + OB_EB);
    unsigned* ET_32 = (unsigned*)(smb + OB_ETB);
    unsigned* G_32  = (unsigned*)(smb + OB_GB);
    unsigned* EU_32 = (unsigned*)(smb + OB_EUB);
    unsigned* EV_32 = (unsigned*)(smb + OB_EVB);

    // ---- load tiles (tf32-prerounded, stride 68); inverse norms inline ----
    {
        const float4* g1 = (const float4*)(X1g + i * 4096);
        const float4* g2 = (const float4*)(X2g + i * 4096);
#pragma unroll
        for (int m = 0; m < 2; m++) {
            int v = tid + m * 512;
            int r = v >> 4;
            int c = (v & 15) << 2;
            float4 a = g1[v];
            float4 b = g2[v];
            float4 ar; ar.x = tf32r(a.x); ar.y = tf32r(a.y);
                       ar.z = tf32r(a.z); ar.w = tf32r(a.w);
            float4 br; br.x = tf32r(b.x); br.y = tf32r(b.y);
                       br.z = tf32r(b.z); br.w = tf32r(b.w);
            *(float4*)(sX1 + r * STF + c) = ar;
            *(float4*)(sX2 + r * STF + c) = br;
            float s1 = a.x * a.x + a.y * a.y + a.z * a.z + a.w * a.w;
            float s2 = b.x * b.x + b.y * b.y + b.z * b.z + b.w * b.w;
#pragma unroll
            for (int o = 8; o; o >>= 1) {
                s1 += __shfl_xor_sync(~0u, s1, o);
                s2 += __shfl_xor_sync(~0u, s2, o);
            }
            if ((tid & 15) == 0) {
                sI1[r] = 1.0f / fmaxf(sqrtf(s1), 1e-8f);
                sI2[r] = 1.0f / fmaxf(sqrtf(s2), 1e-8f);
            }
        }
    }

    // ---- softmax -> q (bf16, stride 72) ----
#pragma unroll 1
    for (int r4 = 0; r4 < 4; r4++) {
        int a = wid * 4 + r4;
        const float* r1 = X1g + (a * 64 + i) * 64;
        const float* r2 = X2g + (a * 64 + i) * 64;
        float x1a = r1[lane], x1b = r1[lane + 32];
        float x2a = r2[lane], x2b = r2[lane + 32];
        {
            float mx = fmaxf(x1a, x1b);
#pragma unroll
            for (int o = 16; o; o >>= 1) mx = fmaxf(mx, __shfl_xor_sync(~0u, mx, o));
            float ex = __expf(x1a - mx), ey = __expf(x1b - mx);
            float s = ex + ey;
#pragma unroll
            for (int o = 16; o; o >>= 1) s += __shfl_xor_sync(~0u, s, o);
            float inv = __fdividef(1.0f, s);
            sQ1b[a * 72 + lane]      = __float2bfloat16(ex * inv + 1e-12f);
            sQ1b[a * 72 + lane + 32] = __float2bfloat16(ey * inv + 1e-12f);
        }
        {
            float mx = fmaxf(x2a, x2b);
#pragma unroll
            for (int o = 16; o; o >>= 1) mx = fmaxf(mx, __shfl_xor_sync(~0u, mx, o));
            float ex = __expf(x2a - mx), ey = __expf(x2b - mx);
            float s = ex + ey;
#pragma unroll
            for (int o = 16; o; o >>= 1) s += __shfl_xor_sync(~0u, s, o);
            float inv = __fdividef(1.0f, s);
            sQ2b[a * 72 + lane]      = __float2bfloat16(ex * inv + 1e-12f);
            sQ2b[a * 72 + lane + 32] = __float2bfloat16(ey * inv + 1e-12f);
        }
    }
    __syncthreads();

    // ---- C = 1 - cosine via tf32 mma (A = x1 rows, Bt = x2 rows) ----
    {
        const int rb = wid & 3, cb = wid >> 2;
        const int g = lane >> 2, tg = lane & 3;
        const int r0 = rb * 16;
        float acc[2][4] = {};
        const int abase = (r0 + g) * STF + tg;
#pragma unroll
        for (int kc = 0; kc < 8; kc++) {
            float a0 = sX1[abase + 8 * kc];
            float a1 = sX1[abase + 8 * STF + 8 * kc];
            float a2 = sX1[abase + 8 * kc + 4];
            float a3 = sX1[abase + 8 * STF + 8 * kc + 4];
#pragma unroll
            for (int t = 0; t < 2; t++) {
                int bbase = (cb * 16 + 8 * t + g) * STF + tg;
                float b0 = sX2[bbase + 8 * kc];
                float b1 = sX2[bbase + 8 * kc + 4];
                mma_tf32(acc[t], a0, a1, a2, a3, b0, b1);
            }
        }
        int rlo = r0 + g, rhi = rlo + 8;
        float i1lo = sI1[rlo], i1hi = sI1[rhi];
#pragma unroll
        for (int t = 0; t < 2; t++) {
            int col = cb * 16 + 8 * t + 2 * tg;
            float i2a = sI2[col], i2b = sI2[col + 1];
            float2 lo, hi;
            lo.x = 1.0f - acc[t][0] * i1lo * i2a;
            lo.y = 1.0f - acc[t][1] * i1lo * i2b;
            hi.x = 1.0f - acc[t][2] * i1hi * i2a;
            hi.y = 1.0f - acc[t][3] * i1hi * i2b;
            *(float2*)(sC + rlo * STF + col) = lo;
            *(float2*)(sC + rhi * STF + col) = hi;
        }
    }
    __syncthreads();

    // ---- fused: per-row minmax -> normalize -> E, E^T, G, 1/rowsum ----
#pragma unroll 1
    for (int r4 = 0; r4 < 4; r4++) {
        int j = wid * 4 + r4;
        float c0v = sC[j * STF + lane];
        float c1v = sC[j * STF + 32 + lane];
        float mn = fminf(c0v, c1v), mx = fmaxf(c0v, c1v);
#pragma unroll
        for (int o = 16; o; o >>= 1) {
            mn = fminf(mn, __shfl_xor_sync(~0u, mn, o));
            mx = fmaxf(mx, __shfl_xor_sync(~0u, mx, o));
        }
        float rinv = 1.0f / (mx - mn);
        float cn0 = (c0v - mn) * rinv;
        float cn1 = (c1v - mn) * rinv;
        float e0 = __expf(-2.0f * cn0);
        float e1 = __expf(-2.0f * cn1);
        sEb[j * 72 + lane]      = __float2bfloat16(e0);
        sEb[j * 72 + lane + 32] = __float2bfloat16(e1);
        sGb[j * 72 + lane]      = __float2bfloat16(e0 * cn0);
        sGb[j * 72 + lane + 32] = __float2bfloat16(e1 * cn1);
        sETb[lane * 74 + j]        = __float2bfloat16(e0);
        sETb[(lane + 32) * 74 + j] = __float2bfloat16(e1);
        float s = e0 + e1;
#pragma unroll
        for (int o = 16; o; o >>= 1) s += __shfl_xor_sync(~0u, s, o);
        if (lane == 0) sRS[j] = __fdividef(1.0f, s);
    }
    __syncthreads();

    // ---- EU0 = q1 * (1/rowsumE) ----
    {
        int a = tid >> 3, j0 = (tid & 7) * 8;
#pragma unroll
        for (int p = 0; p < 4; p++) {
            float2 q = unpack_bf2(Q1_32[a * STW + (j0 >> 1) + p]);
            EU_32[a * STW + (j0 >> 1) + p] =
                pack_bf2(q.x * sRS[j0 + 2 * p], q.y * sRS[j0 + 2 * p + 1]);
        }
    }
    __syncthreads();

    // ---- Sinkhorn: 5 v-phases, 4 u-phases (first u folded) ----
#pragma unroll 1
    for (int it = 0; it < 5; it++) {
        // v: T[a][k] = sum_j EU[a][j] * ET[k][j];  EV = Q2 / T
        mma_div_phase(EU_32, ET_32, STTW, Q2_32, EV_32, wid, lane);
        __syncthreads();
        if (it == 4) break;
        // u: S[a][j] = sum_k EV[a][k] * E[j][k];  EU = Q1 / S
        mma_div_phase(EV_32, E_32, STW, Q1_32, EU_32, wid, lane);
        __syncthreads();
    }

    // ---- final: T2 = EV @ G^T;  loss = sum EU .* T2 ----
    float local = 0.0f;
    {
        const int rb = wid & 3, cb = wid >> 2;
        const int g = lane >> 2, tg = lane & 3;
        const int r0 = rb * 16;
        float acc[2][4] = {};
        const int abase = (r0 + g) * STW + tg;
#pragma unroll
        for (int kc = 0; kc < 4; kc++) {
            unsigned a0_ = EV_32[abase + 8 * kc];
            unsigned a1_ = EV_32[abase + 8 * STW + 8 * kc];
            unsigned a2_ = EV_32[abase + 8 * kc + 4];
            unsigned a3_ = EV_32[abase + 8 * STW + 8 * kc + 4];
#pragma unroll
            for (int tt = 0; tt < 2; tt++) {
                int bbase = (cb * 16 + 8 * tt + g) * STW + tg;
                mma_bf16(acc[tt], a0_, a1_, a2_, a3_,
                         G_32[bbase + 8 * kc], G_32[bbase + 8 * kc + 4]);
            }
        }
#pragma unroll
        for (int tt = 0; tt < 2; tt++) {
            int colw = cb * 8 + 4 * tt + tg;
            int rlo = r0 + g, rhi = rlo + 8;
            float2 el = unpack_bf2(EU_32[rlo * STW + colw]);
            float2 eh = unpack_bf2(EU_32[rhi * STW + colw]);
            local += el.x * acc[tt][0] + el.y * acc[tt][1]
                   + eh.x * acc[tt][2] + eh.y * acc[tt][3];
        }
    }
#pragma unroll
    for (int o = 16; o; o >>= 1) local += __shfl_xor_sync(~0u, local, o);
    if (lane == 0) sRed[wid] = local;
    __syncthreads();

    // ---- publish partial; last block reduces deterministically ----
    if (tid == 0) {
        float tt = 0.0f;
#pragma unroll
        for (int w = 0; w < 16; w++) tt += sRed[w];
        g_partials[blk] = tt;
        __threadfence();
        unsigned int old = atomicAdd(&g_count, 1u);
        sFlag[0] = (old == 127u);
    }
    __syncthreads();
    if (sFlag[0] && wid == 0) {
        __threadfence();
        float v = g_partials[lane] + g_partials[lane + 32]
                + g_partials[lane + 64] + g_partials[lane + 96];
#pragma unroll
        for (int o = 16; o; o >>= 1) v += __shfl_xor_sync(~0u, v, o);
        if (lane == 0) {
            out[0] = v * (1.0f / 8192.0f);
            g_count = 0;
        }
    }
}

extern "C" void kernel_launch(void* const* d_in, const int* in_sizes, int n_in,
                              void* d_out, int out_size)
{
    (void)in_sizes; (void)n_in; (void)out_size;
    cudaFuncSetAttribute(emd_main, cudaFuncAttributeMaxDynamicSharedMemorySize, SMEM_BYTES);
    emd_main<<<128, 512, SMEM_BYTES>>>((const float*)d_in[0], (const float*)d_in[1],
                                       (const float*)d_in[2], (const float*)d_in[3],
                                       (float*)d_out);
}